// round 15
// baseline (speedup 1.0000x reference)
#include <cuda_runtime.h>
#include <stdint.h>

#define NC 80
#define NP 30000
#define NG 800
// gt y-bands (64 px)
#define NYB 16
// pred bins: y-major, then width, then x (x fastest so consecutive preds share y/w)
#define NYBP 8
#define NWBP 2
#define NXBP 32
#define NPBIN (NYBP * NWBP * NXBP)   // 512

// ---------------- scratch (static device globals; no allocation) ----------------
__device__ unsigned int g_sbits[NC * NP];
__device__ unsigned int g_slotinfo[NC * NP];   // (bin<<16) | within-bin slot
__device__ int   g_xhist[NC * NPBIN];
__device__ int   g_base[NC * NPBIN];
__device__ unsigned long long g_best[NC * NG];  // per-gt winner: (score<<32)|~idx
__device__ float g_ap[NC];
// compact boxes in input order
__device__ float4 g_pboxin[(size_t)NC * NP];
// preds sorted by (yband, wclass, xbin)
__device__ float4 g_pbox[(size_t)NC * NP];
__device__ int    g_pidx[NC * NP];
// gts sorted by (yband, x1)
__device__ float4 g_sgbox[NC * NG];
__device__ float  g_sgarea[NC * NG];
__device__ int    g_sgidx[NC * NG];
__device__ float  g_sgx1[NC * NG];
__device__ int    g_gbandoff[NC * (NYB + 1)];
__device__ float  g_gwmax[NC];
__device__ float  g_ghmax[NC];

__device__ __forceinline__ int pbin(float x1, float y1, float w) {
    int xb = max(0, min((int)(x1 * ((float)NXBP / 1024.0f)), NXBP - 1));
    int yb = max(0, min((int)(y1 * ((float)NYBP / 1024.0f)), NYBP - 1));
    int wb = max(0, min((int)((w - 4.0f) * ((float)NWBP / 124.5f)), NWBP - 1));
    return (yb * NWBP + wb) * NXBP + xb;
}

// ---------------- K0: init ----------------
__global__ void k_init() {
    int i = blockIdx.x * blockDim.x + threadIdx.x;
    if (i < NC * NPBIN) g_xhist[i] = 0;
    if (i < NC * NG)    g_best[i] = 0ULL;
}

// ---------------- K1: coalesced pred pass — histogram (atomic return = slot) + stash ----------------
__global__ void __launch_bounds__(256) k_prep(const float* __restrict__ pred) {
    __shared__ float buf[256 * 7];
    int blk0 = blockIdx.x * 256;          // first box of this block
    if (blk0 >= NC * NP) return;
    // coalesced stage: 256 boxes = 1792 floats = 448 float4 (aligned)
    const float4* src = (const float4*)(pred + (size_t)blk0 * 7);
    float4* dst = (float4*)buf;
    for (int v = threadIdx.x; v < 448; v += 256) dst[v] = src[v];
    __syncthreads();

    int i = blk0 + threadIdx.x;
    if (i >= NC * NP) return;
    const float* bp = buf + threadIdx.x * 7;
    float s  = bp[2];
    float x1 = bp[3], y1 = bp[4], x2 = bp[5], y2 = bp[6];
    g_sbits[i]  = __float_as_uint(s);
    g_pboxin[i] = make_float4(x1, y1, x2, y2);
    int c = i / NP;
    int bin = pbin(x1, y1, x2 - x1);
    int slot = atomicAdd(&g_xhist[c * NPBIN + bin], 1);
    g_slotinfo[i] = ((unsigned int)bin << 16) | (unsigned int)slot;
}

// ---------------- K2: per-class ascending exclusive scan of pred bins ----------------
__global__ void k_xscan() {
    __shared__ int sh[NPBIN];
    int c = blockIdx.x, t = threadIdx.x;
    sh[t] = g_xhist[c * NPBIN + t];
    __syncthreads();
    int v = sh[t];
    for (int off = 1; off < NPBIN; off <<= 1) {
        int u = (t >= off) ? sh[t - off] : 0;
        __syncthreads();
        sh[t] += u;
        __syncthreads();
    }
    g_base[c * NPBIN + t] = sh[t] - v;   // exclusive prefix
}

// ---------------- K3: scatter preds into bin order (NO atomics) ----------------
__global__ void k_fscatter() {
    int i = blockIdx.x * blockDim.x + threadIdx.x;
    if (i >= NC * NP) return;
    int c = i / NP, p = i - c * NP;
    unsigned int info = g_slotinfo[i];
    int bin  = (int)(info >> 16);
    int slot = (int)(info & 0xFFFFu);
    int dest = g_base[c * NPBIN + bin] + slot;
    g_pbox[(size_t)c * NP + dest] = g_pboxin[i];
    g_pidx[c * NP + dest] = p;
}

// ---------------- K4: per-class bitonic sort of gts by (yband, x1) ----------------
__global__ void k_gtsort(const float* __restrict__ gt) {
    __shared__ unsigned long long key[1024];
    __shared__ float swm[1024];
    __shared__ float shm[1024];
    int c = blockIdx.x, t = threadIdx.x;
    float w = 0.0f, h = 0.0f;
    if (t < NG) {
        const float* gp = gt + ((size_t)c * NG + t) * 7;
        float x1 = gp[3], y1 = gp[4];
        int band = max(0, min((int)(y1 * ((float)NYB / 1024.0f)), NYB - 1));
        key[t] = ((unsigned long long)band << 44)
               | ((unsigned long long)__float_as_uint(x1) << 12)
               | (unsigned int)t;
        w = gp[5] - x1;
        h = gp[6] - y1;
    } else {
        key[t] = 0xFFFFFFFFFFFFFFFFULL;
    }
    swm[t] = w;
    shm[t] = h;
    __syncthreads();
    for (int k2 = 2; k2 <= 1024; k2 <<= 1) {
        for (int j = k2 >> 1; j > 0; j >>= 1) {
            int ixj = t ^ j;
            if (ixj > t) {
                bool up = ((t & k2) == 0);
                unsigned long long a = key[t], b = key[ixj];
                if ((a > b) == up) { key[t] = b; key[ixj] = a; }
            }
            __syncthreads();
        }
    }
    for (int s = 512; s > 0; s >>= 1) {
        if (t < s) {
            swm[t] = fmaxf(swm[t], swm[t + s]);
            shm[t] = fmaxf(shm[t], shm[t + s]);
        }
        __syncthreads();
    }
    if (t == 0) { g_gwmax[c] = swm[0]; g_ghmax[c] = shm[0]; }
    if (t < NG) {
        int oi = (int)(key[t] & 0xFFFULL);
        const float* gp = gt + ((size_t)c * NG + oi) * 7;
        float x1 = gp[3], y1 = gp[4], x2 = gp[5], y2 = gp[6];
        int o = c * NG + t;
        g_sgbox[o]  = make_float4(x1, y1, x2, y2);
        g_sgarea[o] = (x2 - x1) * (y2 - y1);
        g_sgidx[o]  = oi;
        g_sgx1[o]   = x1;
    }
    // band offsets: first index with band >= b
    if (t <= NYB) {
        unsigned long long thr = (unsigned long long)t << 44;
        int lo = 0, n = 1024;
        while (n > 0) {
            int half = n >> 1, mid = lo + half;
            if (key[mid] < thr) { lo = mid + 1; n -= half + 1; }
            else n = half;
        }
        g_gbandoff[c * (NYB + 1) + t] = min(lo, NG);
    }
}

// ---------------- K5: match — x-window * fine y-band pruning ----------------
#define MB 256
#define PPB (2 * MB)
#define SLACK 0.25f
__global__ void __launch_bounds__(MB) k_match() {
    __shared__ float4 sg[NG];
    __shared__ float  sa[NG];
    __shared__ int    si[NG];
    __shared__ float  sx[NG];
    __shared__ int    soff[NYB + 1];
    __shared__ float  s_wmax, s_hmax;
    int c = blockIdx.y;
    for (int g = threadIdx.x; g < NG; g += MB) {
        int o = c * NG + g;
        sg[g] = g_sgbox[o];
        sa[g] = g_sgarea[o];
        si[g] = g_sgidx[o];
        sx[g] = g_sgx1[o];
    }
    if (threadIdx.x <= NYB) soff[threadIdx.x] = g_gbandoff[c * (NYB + 1) + threadIdx.x];
    if (threadIdx.x == MB - 1) { s_wmax = g_gwmax[c]; s_hmax = g_ghmax[c]; }
    __syncthreads();

    // each warp covers 64 consecutive sorted preds (tight union window)
    int t = threadIdx.x;
    int j0 = blockIdx.x * PPB + (t >> 5) * 64 + (t & 31);
    int j1 = j0 + 32;
    if (j0 >= NP) return;
    bool v1 = j1 < NP;

    size_t cb = (size_t)c * NP;
    float4 A = g_pbox[cb + j0];
    float4 B = g_pbox[cb + (v1 ? j1 : j0)];
    float areaA = (A.z - A.x) * (A.w - A.y);
    float areaB = (B.z - B.x) * (B.w - B.y);

    // valid-winner strips (x and y): overlap must exceed w/3 resp. h/3
    float wA3 = (A.z - A.x) * (1.0f / 3.0f);
    float wB3 = (B.z - B.x) * (1.0f / 3.0f);
    float hA3 = (A.w - A.y) * (1.0f / 3.0f);
    float hB3 = (B.w - B.y) * (1.0f / 3.0f);
    float loX = fminf(A.x + wA3, B.x + wB3) - s_wmax - SLACK;
    float hiX = fmaxf(A.z - wA3, B.z - wB3) + SLACK;
    float loY = fminf(A.y + hA3, B.y + hB3) - s_hmax - SLACK;
    float hiY = fmaxf(A.w - hA3, B.w - hB3) + SLACK;

    int bLo = max(0, min((int)(loY * ((float)NYB / 1024.0f)), NYB - 1));
    int bHi = max(0, min((int)(hiY * ((float)NYB / 1024.0f)), NYB - 1));

    float ai = 0.0f, ad = 1.0f; int ag = 0;
    float bi = 0.0f, bd = 1.0f; int bg = 0;

    for (int b = bLo; b <= bHi; b++) {
        int s0 = soff[b], e0 = soff[b + 1];
        int lo = s0;
        {
            int n = e0 - s0;
            while (n > 0) {
                int half = n >> 1, mid = lo + half;
                if (sx[mid] < loX) { lo = mid + 1; n -= half + 1; }
                else n = half;
            }
        }
        int hi = lo;
        {
            int n = e0 - lo;
            while (n > 0) {
                int half = n >> 1, mid = hi + half;
                if (sx[mid] < hiX) { hi = mid + 1; n -= half + 1; }
                else n = half;
            }
        }
#pragma unroll 4
        for (int g = lo; g < hi; g++) {
            float4 q = sg[g];
            float ga = sa[g];

            float w0 = fminf(A.z, q.z) - fmaxf(A.x, q.x);
            float h0 = fminf(A.w, q.w) - fmaxf(A.y, q.y);
            float i0 = fmaxf(w0, 0.0f) * fmaxf(h0, 0.0f);
            float d0 = (areaA + ga) - i0;
            if (i0 * ad > ai * d0) { ai = i0; ad = d0; ag = g; }

            float w1 = fminf(B.z, q.z) - fmaxf(B.x, q.x);
            float h1 = fminf(B.w, q.w) - fmaxf(B.y, q.y);
            float i1 = fmaxf(w1, 0.0f) * fmaxf(h1, 0.0f);
            float d1 = (areaB + ga) - i1;
            if (i1 * bd > bi * d1) { bi = i1; bd = d1; bg = g; }
        }
    }

    {
        float iou = ai / (ad + 1e-9f);
        if (iou > 0.5f) {
            int agi = si[ag];
            unsigned int op = (unsigned int)g_pidx[c * NP + j0];
            unsigned long long key =
                ((unsigned long long)g_sbits[c * NP + op] << 32) | (unsigned int)(~op);
            atomicMax(&g_best[c * NG + agi], key);
        }
    }
    if (v1) {
        float iou = bi / (bd + 1e-9f);
        if (iou > 0.5f) {
            int bgi = si[bg];
            unsigned int op = (unsigned int)g_pidx[c * NP + j1];
            unsigned long long key =
                ((unsigned long long)g_sbits[c * NP + op] << 32) | (unsigned int)(~op);
            atomicMax(&g_best[c * NG + bgi], key);
        }
    }
}

// ---------------- K6: per-class winner ranks + AP (fused) ----------------
__global__ void __launch_bounds__(1024) k_rankap() {
    __shared__ unsigned long long wkey[1024];
    __shared__ int    cnt[1026];
    __shared__ int    ssum[1024];
    __shared__ double red[1024];
    int c = blockIdx.x, t = threadIdx.x;

    unsigned long long k0 = (t < NG) ? g_best[c * NG + t] : 0ULL;
    wkey[t] = k0;
    ssum[t] = (k0 != 0ULL) ? 1 : 0;
    __syncthreads();
    // count winners
    for (int s = 512; s > 0; s >>= 1) {
        if (t < s) ssum[t] += ssum[t + s];
        __syncthreads();
    }
    int n_w = ssum[0];
    __syncthreads();

    // bitonic sort ascending: zeros (empties) land in front, winners in [off,1024)
    for (int k2 = 2; k2 <= 1024; k2 <<= 1) {
        for (int j = k2 >> 1; j > 0; j >>= 1) {
            int ixj = t ^ j;
            if (ixj > t) {
                bool up = ((t & k2) == 0);
                unsigned long long a = wkey[t], b = wkey[ixj];
                if ((a > b) == up) { wkey[t] = b; wkey[ixj] = a; }
            }
            __syncthreads();
        }
    }
    int off = 1024 - n_w;
    if (t <= n_w) cnt[t] = 0;
    __syncthreads();

    if (n_w > 0) {
        // every pred bins itself among the sorted winner keys
        for (int base = 0; base < NP; base += 1024) {
            int i = base + t;
            if (i < NP) {
                unsigned long long key =
                    ((unsigned long long)g_sbits[c * NP + i] << 32)
                    | (unsigned int)(~(unsigned int)i);
                int lo = off, n = n_w;
                while (n > 0) {
                    int half = n >> 1, mid = lo + half;
                    if (wkey[mid] < key) { lo = mid + 1; n -= half + 1; }
                    else n = half;
                }
                atomicAdd(&cnt[lo - off], 1);   // pos in [0, n_w]
            }
        }
    }
    __syncthreads();

    // inclusive suffix sum of cnt[0..n_w]
    ssum[t] = (t <= n_w) ? cnt[t] : 0;
    __syncthreads();
    for (int o2 = 1; o2 < 1024; o2 <<= 1) {
        int v = (t + o2 < 1024) ? ssum[t + o2] : 0;
        __syncthreads();
        ssum[t] += v;
        __syncthreads();
    }

    // winner j (ascending key) has rank r = ssum[j+1]; ctp at its rank = n_w - j
    double term = 0.0;
    if (t < n_w) {
        int r = ssum[t + 1];
        int ctp = n_w - t;
        if (r > 0) {
            float p1 = (float)ctp / (float)(r + 1);
            float p0 = (float)(ctp - 1) / (float)r;
            term = 0.5 * ((double)p1 + (double)p0);
        }
    }
    red[t] = term;
    __syncthreads();
    for (int s = 512; s > 0; s >>= 1) {
        if (t < s) red[t] += red[t + s];
        __syncthreads();
    }
    if (t == 0) g_ap[c] = (float)(red[0] / (double)NG);
}

// ---------------- K7: mean over classes ----------------
__global__ void k_mean(float* __restrict__ out) {
    __shared__ double red[128];
    int t = threadIdx.x;
    red[t] = (t < NC) ? (double)g_ap[t] : 0.0;
    __syncthreads();
    for (int s = 64; s > 0; s >>= 1) {
        if (t < s) red[t] += red[t + s];
        __syncthreads();
    }
    if (t == 0) out[0] = (float)(red[0] / (double)NC);
}

// ---------------- launcher ----------------
extern "C" void kernel_launch(void* const* d_in, const int* in_sizes, int n_in,
                              void* d_out, int out_size) {
    const float* pred;
    const float* gt;
    if (in_sizes[0] == NC * NP * 7) { pred = (const float*)d_in[0]; gt = (const float*)d_in[1]; }
    else                            { pred = (const float*)d_in[1]; gt = (const float*)d_in[0]; }

    const int NTOT = NC * NP;
    k_init<<<(NC * NG + 255) / 256, 256>>>();
    k_prep<<<(NTOT + 255) / 256, 256>>>(pred);
    k_xscan<<<NC, NPBIN>>>();
    k_fscatter<<<(NTOT + 255) / 256, 256>>>();
    k_gtsort<<<NC, 1024>>>(gt);
    dim3 mg((NP + PPB - 1) / PPB, NC);
    k_match<<<mg, MB>>>();
    k_rankap<<<NC, 1024>>>();
    k_mean<<<1, 128>>>((float*)d_out);
}

// round 16
// speedup vs baseline: 1.0453x; 1.0453x over previous
#include <cuda_runtime.h>
#include <stdint.h>

#define NC 80
#define NP 30000
#define NG 800
// gt y-bands (64 px)
#define NYB 16
// pred bins: y-major, then width, then x (x fastest so consecutive preds share y/w)
#define NYBP 8
#define NWBP 2
#define NXBP 32
#define NPBIN (NYBP * NWBP * NXBP)   // 512

// ---------------- scratch (static device globals; no allocation) ----------------
__device__ unsigned int g_sbits[NC * NP];
__device__ unsigned int g_slotinfo[NC * NP];   // (bin<<16) | within-bin slot
__device__ int   g_xhist[NC * NPBIN];
__device__ int   g_base[NC * NPBIN];
__device__ unsigned long long g_best[NC * NG];  // per-gt winner: (score<<32)|~idx
__device__ float g_ap[NC];
// compact boxes in input order
__device__ float4 g_pboxin[(size_t)NC * NP];
// preds sorted by (yband, wclass, xbin)
__device__ float4 g_pbox[(size_t)NC * NP];
__device__ int    g_pidx[NC * NP];
// gts sorted by (yband, x1)
__device__ float4 g_sgbox[NC * NG];
__device__ float  g_sgarea[NC * NG];
__device__ int    g_sgidx[NC * NG];
__device__ float  g_sgx1[NC * NG];
__device__ int    g_gbandoff[NC * (NYB + 1)];
__device__ float  g_gwmax[NC];
__device__ float  g_ghmax[NC];

__device__ __forceinline__ int pbin(float x1, float y1, float w) {
    int xb = max(0, min((int)(x1 * ((float)NXBP / 1024.0f)), NXBP - 1));
    int yb = max(0, min((int)(y1 * ((float)NYBP / 1024.0f)), NYBP - 1));
    int wb = max(0, min((int)((w - 4.0f) * ((float)NWBP / 124.5f)), NWBP - 1));
    return (yb * NWBP + wb) * NXBP + xb;
}

// ---------------- K0: init ----------------
__global__ void k_init() {
    int i = blockIdx.x * blockDim.x + threadIdx.x;
    if (i < NC * NPBIN) g_xhist[i] = 0;
    if (i < NC * NG)    g_best[i] = 0ULL;
}

// ---------------- K1: coalesced pred pass — histogram (atomic return = slot) + stash ----------------
__global__ void __launch_bounds__(256) k_prep(const float* __restrict__ pred) {
    __shared__ float buf[256 * 7];
    int blk0 = blockIdx.x * 256;          // first box of this block
    if (blk0 >= NC * NP) return;
    // coalesced stage: 256 boxes = 1792 floats = 448 float4 (aligned)
    const float4* src = (const float4*)(pred + (size_t)blk0 * 7);
    float4* dst = (float4*)buf;
    for (int v = threadIdx.x; v < 448; v += 256) dst[v] = src[v];
    __syncthreads();

    int i = blk0 + threadIdx.x;
    if (i >= NC * NP) return;
    const float* bp = buf + threadIdx.x * 7;
    float s  = bp[2];
    float x1 = bp[3], y1 = bp[4], x2 = bp[5], y2 = bp[6];
    g_sbits[i]  = __float_as_uint(s);
    g_pboxin[i] = make_float4(x1, y1, x2, y2);
    int c = i / NP;
    int bin = pbin(x1, y1, x2 - x1);
    int slot = atomicAdd(&g_xhist[c * NPBIN + bin], 1);
    g_slotinfo[i] = ((unsigned int)bin << 16) | (unsigned int)slot;
}

// ---------------- K2: per-class ascending exclusive scan of pred bins ----------------
__global__ void k_xscan() {
    __shared__ int sh[NPBIN];
    int c = blockIdx.x, t = threadIdx.x;
    sh[t] = g_xhist[c * NPBIN + t];
    __syncthreads();
    int v = sh[t];
    for (int off = 1; off < NPBIN; off <<= 1) {
        int u = (t >= off) ? sh[t - off] : 0;
        __syncthreads();
        sh[t] += u;
        __syncthreads();
    }
    g_base[c * NPBIN + t] = sh[t] - v;   // exclusive prefix
}

// ---------------- K3: scatter preds into bin order (NO atomics) ----------------
__global__ void k_fscatter() {
    int i = blockIdx.x * blockDim.x + threadIdx.x;
    if (i >= NC * NP) return;
    int c = i / NP, p = i - c * NP;
    unsigned int info = g_slotinfo[i];
    int bin  = (int)(info >> 16);
    int slot = (int)(info & 0xFFFFu);
    int dest = g_base[c * NPBIN + bin] + slot;
    g_pbox[(size_t)c * NP + dest] = g_pboxin[i];
    g_pidx[c * NP + dest] = p;
}

// ---------------- K4: per-class bitonic sort of gts by (yband, x1) ----------------
__global__ void k_gtsort(const float* __restrict__ gt) {
    __shared__ unsigned long long key[1024];
    __shared__ float swm[1024];
    __shared__ float shm[1024];
    int c = blockIdx.x, t = threadIdx.x;
    float w = 0.0f, h = 0.0f;
    if (t < NG) {
        const float* gp = gt + ((size_t)c * NG + t) * 7;
        float x1 = gp[3], y1 = gp[4];
        int band = max(0, min((int)(y1 * ((float)NYB / 1024.0f)), NYB - 1));
        key[t] = ((unsigned long long)band << 44)
               | ((unsigned long long)__float_as_uint(x1) << 12)
               | (unsigned int)t;
        w = gp[5] - x1;
        h = gp[6] - y1;
    } else {
        key[t] = 0xFFFFFFFFFFFFFFFFULL;
    }
    swm[t] = w;
    shm[t] = h;
    __syncthreads();
    for (int k2 = 2; k2 <= 1024; k2 <<= 1) {
        for (int j = k2 >> 1; j > 0; j >>= 1) {
            int ixj = t ^ j;
            if (ixj > t) {
                bool up = ((t & k2) == 0);
                unsigned long long a = key[t], b = key[ixj];
                if ((a > b) == up) { key[t] = b; key[ixj] = a; }
            }
            __syncthreads();
        }
    }
    for (int s = 512; s > 0; s >>= 1) {
        if (t < s) {
            swm[t] = fmaxf(swm[t], swm[t + s]);
            shm[t] = fmaxf(shm[t], shm[t + s]);
        }
        __syncthreads();
    }
    if (t == 0) { g_gwmax[c] = swm[0]; g_ghmax[c] = shm[0]; }
    if (t < NG) {
        int oi = (int)(key[t] & 0xFFFULL);
        const float* gp = gt + ((size_t)c * NG + oi) * 7;
        float x1 = gp[3], y1 = gp[4], x2 = gp[5], y2 = gp[6];
        int o = c * NG + t;
        g_sgbox[o]  = make_float4(x1, y1, x2, y2);
        g_sgarea[o] = (x2 - x1) * (y2 - y1);
        g_sgidx[o]  = oi;
        g_sgx1[o]   = x1;
    }
    // band offsets: first index with band >= b
    if (t <= NYB) {
        unsigned long long thr = (unsigned long long)t << 44;
        int lo = 0, n = 1024;
        while (n > 0) {
            int half = n >> 1, mid = lo + half;
            if (key[mid] < thr) { lo = mid + 1; n -= half + 1; }
            else n = half;
        }
        g_gbandoff[c * (NYB + 1) + t] = min(lo, NG);
    }
}

// ---------------- K5: match — flag-only inner loop, rare argmax branch ----------------
#define MB 256
#define PPB (2 * MB)
#define SLACK 0.25f
__global__ void __launch_bounds__(MB) k_match() {
    __shared__ float4 sg[NG];
    __shared__ float  sa[NG];
    __shared__ int    si[NG];
    __shared__ float  sx[NG];
    __shared__ int    soff[NYB + 1];
    __shared__ float  s_wmax, s_hmax;
    int c = blockIdx.y;
    for (int g = threadIdx.x; g < NG; g += MB) {
        int o = c * NG + g;
        sg[g] = g_sgbox[o];
        sa[g] = g_sgarea[o];
        si[g] = g_sgidx[o];
        sx[g] = g_sgx1[o];
    }
    if (threadIdx.x <= NYB) soff[threadIdx.x] = g_gbandoff[c * (NYB + 1) + threadIdx.x];
    if (threadIdx.x == MB - 1) { s_wmax = g_gwmax[c]; s_hmax = g_ghmax[c]; }
    __syncthreads();

    // each warp covers 64 consecutive sorted preds (tight union window)
    int t = threadIdx.x;
    int j0 = blockIdx.x * PPB + (t >> 5) * 64 + (t & 31);
    int j1 = j0 + 32;
    if (j0 >= NP) return;
    bool v1 = j1 < NP;

    size_t cb = (size_t)c * NP;
    float4 A = g_pbox[cb + j0];
    float4 B = g_pbox[cb + (v1 ? j1 : j0)];
    float areaA = (A.z - A.x) * (A.w - A.y);
    float areaB = (B.z - B.x) * (B.w - B.y);

    // valid-winner strips (x and y): overlap must exceed w/3 resp. h/3
    float wA3 = (A.z - A.x) * (1.0f / 3.0f);
    float wB3 = (B.z - B.x) * (1.0f / 3.0f);
    float hA3 = (A.w - A.y) * (1.0f / 3.0f);
    float hB3 = (B.w - B.y) * (1.0f / 3.0f);
    float loX = fminf(A.x + wA3, B.x + wB3) - s_wmax - SLACK;
    float hiX = fmaxf(A.z - wA3, B.z - wB3) + SLACK;
    float loY = fminf(A.y + hA3, B.y + hB3) - s_hmax - SLACK;
    float hiY = fmaxf(A.w - hA3, B.w - hB3) + SLACK;

    int bLo = max(0, min((int)(loY * ((float)NYB / 1024.0f)), NYB - 1));
    int bHi = max(0, min((int)(hiY * ((float)NYB / 1024.0f)), NYB - 1));

    // best-so-far among VALID (iou>0.5) gts only; rare updates
    float ai = 0.0f, ad = 1.0f; int ag = -1;
    float bi = 0.0f, bd = 1.0f; int bg = -1;

    for (int b = bLo; b <= bHi; b++) {
        int s0 = soff[b], e0 = soff[b + 1];
        int lo = s0;
        {
            int n = e0 - s0;
            while (n > 0) {
                int half = n >> 1, mid = lo + half;
                if (sx[mid] < loX) { lo = mid + 1; n -= half + 1; }
                else n = half;
            }
        }
        int hi = lo;
        {
            int n = e0 - lo;
            while (n > 0) {
                int half = n >> 1, mid = hi + half;
                if (sx[mid] < hiX) { hi = mid + 1; n -= half + 1; }
                else n = half;
            }
        }
#pragma unroll 4
        for (int g = lo; g < hi; g++) {
            float4 q = sg[g];
            float ga = sa[g];
            float sA = areaA + ga;
            float sB = areaB + ga;

            float w0 = fminf(A.z, q.z) - fmaxf(A.x, q.x);
            float h0 = fminf(A.w, q.w) - fmaxf(A.y, q.y);
            float i0 = fmaxf(w0, 0.0f) * fmaxf(h0, 0.0f);
            float w1 = fminf(B.z, q.z) - fmaxf(B.x, q.x);
            float h1 = fminf(B.w, q.w) - fmaxf(B.y, q.y);
            float i1 = fmaxf(w1, 0.0f) * fmaxf(h1, 0.0f);

            // iou > 0.5  <=>  3*inter > areaP + areaG
            bool f0 = 3.0f * i0 > sA;
            bool f1 = 3.0f * i1 > sB;
            if (f0 | f1) {                 // rare (~3% of warp-iterations)
                if (f0) {
                    float d0 = sA - i0;
                    if (i0 * ad > ai * d0) { ai = i0; ad = d0; ag = g; }
                }
                if (f1) {
                    float d1 = sB - i1;
                    if (i1 * bd > bi * d1) { bi = i1; bd = d1; bg = g; }
                }
            }
        }
    }

    if (ag >= 0) {
        int agi = si[ag];
        unsigned int op = (unsigned int)g_pidx[c * NP + j0];
        unsigned long long key =
            ((unsigned long long)g_sbits[c * NP + op] << 32) | (unsigned int)(~op);
        atomicMax(&g_best[c * NG + agi], key);
    }
    if (v1 && bg >= 0) {
        int bgi = si[bg];
        unsigned int op = (unsigned int)g_pidx[c * NP + j1];
        unsigned long long key =
            ((unsigned long long)g_sbits[c * NP + op] << 32) | (unsigned int)(~op);
        atomicMax(&g_best[c * NG + bgi], key);
    }
}

// ---------------- K6: per-class winner ranks + AP (fused) ----------------
__global__ void __launch_bounds__(1024) k_rankap() {
    __shared__ unsigned long long wkey[1024];
    __shared__ int    cnt[1026];
    __shared__ int    ssum[1024];
    __shared__ double red[1024];
    int c = blockIdx.x, t = threadIdx.x;

    unsigned long long k0 = (t < NG) ? g_best[c * NG + t] : 0ULL;
    wkey[t] = k0;
    ssum[t] = (k0 != 0ULL) ? 1 : 0;
    __syncthreads();
    // count winners
    for (int s = 512; s > 0; s >>= 1) {
        if (t < s) ssum[t] += ssum[t + s];
        __syncthreads();
    }
    int n_w = ssum[0];
    __syncthreads();

    // bitonic sort ascending: zeros (empties) land in front, winners in [off,1024)
    for (int k2 = 2; k2 <= 1024; k2 <<= 1) {
        for (int j = k2 >> 1; j > 0; j >>= 1) {
            int ixj = t ^ j;
            if (ixj > t) {
                bool up = ((t & k2) == 0);
                unsigned long long a = wkey[t], b = wkey[ixj];
                if ((a > b) == up) { wkey[t] = b; wkey[ixj] = a; }
            }
            __syncthreads();
        }
    }
    int off = 1024 - n_w;
    if (t <= n_w) cnt[t] = 0;
    __syncthreads();

    if (n_w > 0) {
        // every pred bins itself among the sorted winner keys
        for (int base = 0; base < NP; base += 1024) {
            int i = base + t;
            if (i < NP) {
                unsigned long long key =
                    ((unsigned long long)g_sbits[c * NP + i] << 32)
                    | (unsigned int)(~(unsigned int)i);
                int lo = off, n = n_w;
                while (n > 0) {
                    int half = n >> 1, mid = lo + half;
                    if (wkey[mid] < key) { lo = mid + 1; n -= half + 1; }
                    else n = half;
                }
                atomicAdd(&cnt[lo - off], 1);   // pos in [0, n_w]
            }
        }
    }
    __syncthreads();

    // inclusive suffix sum of cnt[0..n_w]
    ssum[t] = (t <= n_w) ? cnt[t] : 0;
    __syncthreads();
    for (int o2 = 1; o2 < 1024; o2 <<= 1) {
        int v = (t + o2 < 1024) ? ssum[t + o2] : 0;
        __syncthreads();
        ssum[t] += v;
        __syncthreads();
    }

    // winner j (ascending key) has rank r = ssum[j+1]; ctp at its rank = n_w - j
    double term = 0.0;
    if (t < n_w) {
        int r = ssum[t + 1];
        int ctp = n_w - t;
        if (r > 0) {
            float p1 = (float)ctp / (float)(r + 1);
            float p0 = (float)(ctp - 1) / (float)r;
            term = 0.5 * ((double)p1 + (double)p0);
        }
    }
    red[t] = term;
    __syncthreads();
    for (int s = 512; s > 0; s >>= 1) {
        if (t < s) red[t] += red[t + s];
        __syncthreads();
    }
    if (t == 0) g_ap[c] = (float)(red[0] / (double)NG);
}

// ---------------- K7: mean over classes ----------------
__global__ void k_mean(float* __restrict__ out) {
    __shared__ double red[128];
    int t = threadIdx.x;
    red[t] = (t < NC) ? (double)g_ap[t] : 0.0;
    __syncthreads();
    for (int s = 64; s > 0; s >>= 1) {
        if (t < s) red[t] += red[t + s];
        __syncthreads();
    }
    if (t == 0) out[0] = (float)(red[0] / (double)NC);
}

// ---------------- launcher ----------------
extern "C" void kernel_launch(void* const* d_in, const int* in_sizes, int n_in,
                              void* d_out, int out_size) {
    const float* pred;
    const float* gt;
    if (in_sizes[0] == NC * NP * 7) { pred = (const float*)d_in[0]; gt = (const float*)d_in[1]; }
    else                            { pred = (const float*)d_in[1]; gt = (const float*)d_in[0]; }

    const int NTOT = NC * NP;
    k_init<<<(NC * NG + 255) / 256, 256>>>();
    k_prep<<<(NTOT + 255) / 256, 256>>>(pred);
    k_xscan<<<NC, NPBIN>>>();
    k_fscatter<<<(NTOT + 255) / 256, 256>>>();
    k_gtsort<<<NC, 1024>>>(gt);
    dim3 mg((NP + PPB - 1) / PPB, NC);
    k_match<<<mg, MB>>>();
    k_rankap<<<NC, 1024>>>();
    k_mean<<<1, 128>>>((float*)d_out);
}

// round 17
// speedup vs baseline: 1.0761x; 1.0295x over previous
#include <cuda_runtime.h>
#include <stdint.h>

#define NC 80
#define NP 30000
#define NG 800
// gt y-bands (64 px)
#define NYB 16
// pred bins: y-major, then width, then x (x fastest so consecutive preds share y/w)
#define NYBP 8
#define NWBP 2
#define NXBP 32
#define NPBIN (NYBP * NWBP * NXBP)   // 512

// ---------------- scratch (static device globals; no allocation) ----------------
__device__ unsigned int g_sbits[NC * NP];
__device__ unsigned int g_slotinfo[NC * NP];   // (bin<<16) | within-bin slot
__device__ int   g_xhist[NC * NPBIN];
__device__ int   g_base[NC * NPBIN];
__device__ unsigned long long g_best[NC * NG];  // per-gt winner: (score<<32)|~idx
__device__ float g_ap[NC];
// compact boxes in input order
__device__ float4 g_pboxin[(size_t)NC * NP];
// preds sorted by (yband, wclass, xbin)
__device__ float4 g_pbox[(size_t)NC * NP];
__device__ int    g_pidx[NC * NP];
// gts sorted by (yband, x1)
__device__ float4 g_sgbox[NC * NG];
__device__ float  g_sgarea[NC * NG];
__device__ int    g_sgidx[NC * NG];
__device__ float  g_sgx1[NC * NG];
__device__ int    g_gbandoff[NC * (NYB + 1)];
__device__ float  g_gwmax[NC];
__device__ float  g_ghmax[NC];

__device__ __forceinline__ int pbin(float x1, float y1, float w) {
    int xb = max(0, min((int)(x1 * ((float)NXBP / 1024.0f)), NXBP - 1));
    int yb = max(0, min((int)(y1 * ((float)NYBP / 1024.0f)), NYBP - 1));
    int wb = max(0, min((int)((w - 4.0f) * ((float)NWBP / 124.5f)), NWBP - 1));
    return (yb * NWBP + wb) * NXBP + xb;
}

__device__ __forceinline__ float wredmin(float v) {
#pragma unroll
    for (int o = 16; o > 0; o >>= 1) v = fminf(v, __shfl_xor_sync(0xffffffffu, v, o));
    return v;
}
__device__ __forceinline__ float wredmax(float v) {
#pragma unroll
    for (int o = 16; o > 0; o >>= 1) v = fmaxf(v, __shfl_xor_sync(0xffffffffu, v, o));
    return v;
}

// ---------------- K0: init ----------------
__global__ void k_init() {
    int i = blockIdx.x * blockDim.x + threadIdx.x;
    if (i < NC * NPBIN) g_xhist[i] = 0;
    if (i < NC * NG)    g_best[i] = 0ULL;
}

// ---------------- K1: coalesced pred pass — histogram (atomic return = slot) + stash ----------------
__global__ void __launch_bounds__(256) k_prep(const float* __restrict__ pred) {
    __shared__ float buf[256 * 7];
    int blk0 = blockIdx.x * 256;          // first box of this block
    if (blk0 >= NC * NP) return;
    // coalesced stage: 256 boxes = 1792 floats = 448 float4 (aligned)
    const float4* src = (const float4*)(pred + (size_t)blk0 * 7);
    float4* dst = (float4*)buf;
    for (int v = threadIdx.x; v < 448; v += 256) dst[v] = src[v];
    __syncthreads();

    int i = blk0 + threadIdx.x;
    if (i >= NC * NP) return;
    const float* bp = buf + threadIdx.x * 7;
    float s  = bp[2];
    float x1 = bp[3], y1 = bp[4], x2 = bp[5], y2 = bp[6];
    g_sbits[i]  = __float_as_uint(s);
    g_pboxin[i] = make_float4(x1, y1, x2, y2);
    int c = i / NP;
    int bin = pbin(x1, y1, x2 - x1);
    int slot = atomicAdd(&g_xhist[c * NPBIN + bin], 1);
    g_slotinfo[i] = ((unsigned int)bin << 16) | (unsigned int)slot;
}

// ---------------- K2: per-class ascending exclusive scan of pred bins ----------------
__global__ void k_xscan() {
    __shared__ int sh[NPBIN];
    int c = blockIdx.x, t = threadIdx.x;
    sh[t] = g_xhist[c * NPBIN + t];
    __syncthreads();
    int v = sh[t];
    for (int off = 1; off < NPBIN; off <<= 1) {
        int u = (t >= off) ? sh[t - off] : 0;
        __syncthreads();
        sh[t] += u;
        __syncthreads();
    }
    g_base[c * NPBIN + t] = sh[t] - v;   // exclusive prefix
}

// ---------------- K3: scatter preds into bin order (NO atomics) ----------------
__global__ void k_fscatter() {
    int i = blockIdx.x * blockDim.x + threadIdx.x;
    if (i >= NC * NP) return;
    int c = i / NP, p = i - c * NP;
    unsigned int info = g_slotinfo[i];
    int bin  = (int)(info >> 16);
    int slot = (int)(info & 0xFFFFu);
    int dest = g_base[c * NPBIN + bin] + slot;
    g_pbox[(size_t)c * NP + dest] = g_pboxin[i];
    g_pidx[c * NP + dest] = p;
}

// ---------------- K4: per-class bitonic sort of gts by (yband, x1) ----------------
__global__ void k_gtsort(const float* __restrict__ gt) {
    __shared__ unsigned long long key[1024];
    __shared__ float swm[1024];
    __shared__ float shm[1024];
    int c = blockIdx.x, t = threadIdx.x;
    float w = 0.0f, h = 0.0f;
    if (t < NG) {
        const float* gp = gt + ((size_t)c * NG + t) * 7;
        float x1 = gp[3], y1 = gp[4];
        int band = max(0, min((int)(y1 * ((float)NYB / 1024.0f)), NYB - 1));
        key[t] = ((unsigned long long)band << 44)
               | ((unsigned long long)__float_as_uint(x1) << 12)
               | (unsigned int)t;
        w = gp[5] - x1;
        h = gp[6] - y1;
    } else {
        key[t] = 0xFFFFFFFFFFFFFFFFULL;
    }
    swm[t] = w;
    shm[t] = h;
    __syncthreads();
    for (int k2 = 2; k2 <= 1024; k2 <<= 1) {
        for (int j = k2 >> 1; j > 0; j >>= 1) {
            int ixj = t ^ j;
            if (ixj > t) {
                bool up = ((t & k2) == 0);
                unsigned long long a = key[t], b = key[ixj];
                if ((a > b) == up) { key[t] = b; key[ixj] = a; }
            }
            __syncthreads();
        }
    }
    for (int s = 512; s > 0; s >>= 1) {
        if (t < s) {
            swm[t] = fmaxf(swm[t], swm[t + s]);
            shm[t] = fmaxf(shm[t], shm[t + s]);
        }
        __syncthreads();
    }
    if (t == 0) { g_gwmax[c] = swm[0]; g_ghmax[c] = shm[0]; }
    if (t < NG) {
        int oi = (int)(key[t] & 0xFFFULL);
        const float* gp = gt + ((size_t)c * NG + oi) * 7;
        float x1 = gp[3], y1 = gp[4], x2 = gp[5], y2 = gp[6];
        int o = c * NG + t;
        g_sgbox[o]  = make_float4(x1, y1, x2, y2);
        g_sgarea[o] = (x2 - x1) * (y2 - y1);
        g_sgidx[o]  = oi;
        g_sgx1[o]   = x1;
    }
    // band offsets: first index with band >= b
    if (t <= NYB) {
        unsigned long long thr = (unsigned long long)t << 44;
        int lo = 0, n = 1024;
        while (n > 0) {
            int half = n >> 1, mid = lo + half;
            if (key[mid] < thr) { lo = mid + 1; n -= half + 1; }
            else n = half;
        }
        g_gbandoff[c * (NYB + 1) + t] = min(lo, NG);
    }
}

// ---------------- K5: match — warp-uniform windows, flag-only inner loop ----------------
#define MB 256
#define PPB (2 * MB)
#define SLACK 0.25f
__global__ void __launch_bounds__(MB) k_match() {
    __shared__ float4 sg[NG];
    __shared__ float  sa[NG];
    __shared__ int    si[NG];
    __shared__ float  sx[NG];
    __shared__ int    soff[NYB + 1];
    __shared__ float  s_wmax, s_hmax;
    int c = blockIdx.y;
    for (int g = threadIdx.x; g < NG; g += MB) {
        int o = c * NG + g;
        sg[g] = g_sgbox[o];
        sa[g] = g_sgarea[o];
        si[g] = g_sgidx[o];
        sx[g] = g_sgx1[o];
    }
    if (threadIdx.x <= NYB) soff[threadIdx.x] = g_gbandoff[c * (NYB + 1) + threadIdx.x];
    if (threadIdx.x == MB - 1) { s_wmax = g_gwmax[c]; s_hmax = g_ghmax[c]; }
    __syncthreads();

    // each warp covers 64 consecutive sorted preds; lanes clamped so ALL participate in shuffles
    int t = threadIdx.x;
    int j0 = blockIdx.x * PPB + (t >> 5) * 64 + (t & 31);
    int j1 = j0 + 32;
    int jj0 = min(j0, NP - 1);
    int jj1 = min(j1, NP - 1);
    bool u0 = j0 < NP, u1 = j1 < NP;

    size_t cb = (size_t)c * NP;
    float4 A = g_pbox[cb + jj0];
    float4 B = g_pbox[cb + jj1];
    float areaA = (A.z - A.x) * (A.w - A.y);
    float areaB = (B.z - B.x) * (B.w - B.y);

    // valid-winner strips (x and y): overlap must exceed w/3 resp. h/3
    float wA3 = (A.z - A.x) * (1.0f / 3.0f);
    float wB3 = (B.z - B.x) * (1.0f / 3.0f);
    float hA3 = (A.w - A.y) * (1.0f / 3.0f);
    float hB3 = (B.w - B.y) * (1.0f / 3.0f);
    float loX = fminf(A.x + wA3, B.x + wB3) - s_wmax - SLACK;
    float hiX = fmaxf(A.z - wA3, B.z - wB3) + SLACK;
    float loY = fminf(A.y + hA3, B.y + hB3) - s_hmax - SLACK;
    float hiY = fmaxf(A.w - hA3, B.w - hB3) + SLACK;

    // warp-union: uniform windows -> uniform searches, uniform loop bounds
    loX = wredmin(loX); hiX = wredmax(hiX);
    loY = wredmin(loY); hiY = wredmax(hiY);

    int bLo = max(0, min((int)(loY * ((float)NYB / 1024.0f)), NYB - 1));
    int bHi = max(0, min((int)(hiY * ((float)NYB / 1024.0f)), NYB - 1));

    // best-so-far among VALID (iou>0.5) gts only; rare updates
    float ai = 0.0f, ad = 1.0f; int ag = -1;
    float bi = 0.0f, bd = 1.0f; int bg = -1;

    for (int b = bLo; b <= bHi; b++) {
        int s0 = soff[b], e0 = soff[b + 1];
        int lo = s0;
        {
            int n = e0 - s0;
            while (n > 0) {
                int half = n >> 1, mid = lo + half;
                if (sx[mid] < loX) { lo = mid + 1; n -= half + 1; }
                else n = half;
            }
        }
        int hi = lo;
        {
            int n = e0 - lo;
            while (n > 0) {
                int half = n >> 1, mid = hi + half;
                if (sx[mid] < hiX) { hi = mid + 1; n -= half + 1; }
                else n = half;
            }
        }
#pragma unroll 4
        for (int g = lo; g < hi; g++) {
            float4 q = sg[g];
            float ga = sa[g];
            float sA = areaA + ga;
            float sB = areaB + ga;

            float w0 = fminf(A.z, q.z) - fmaxf(A.x, q.x);
            float h0 = fminf(A.w, q.w) - fmaxf(A.y, q.y);
            float i0 = fmaxf(w0, 0.0f) * fmaxf(h0, 0.0f);
            float w1 = fminf(B.z, q.z) - fmaxf(B.x, q.x);
            float h1 = fminf(B.w, q.w) - fmaxf(B.y, q.y);
            float i1 = fmaxf(w1, 0.0f) * fmaxf(h1, 0.0f);

            // iou > 0.5  <=>  3*inter > areaP + areaG
            bool f0 = 3.0f * i0 > sA;
            bool f1 = 3.0f * i1 > sB;
            if (f0 | f1) {                 // rare
                if (f0) {
                    float d0 = sA - i0;
                    if (i0 * ad > ai * d0) { ai = i0; ad = d0; ag = g; }
                }
                if (f1) {
                    float d1 = sB - i1;
                    if (i1 * bd > bi * d1) { bi = i1; bd = d1; bg = g; }
                }
            }
        }
    }

    if (u0 && ag >= 0) {
        int agi = si[ag];
        unsigned int op = (unsigned int)g_pidx[c * NP + j0];
        unsigned long long key =
            ((unsigned long long)g_sbits[c * NP + op] << 32) | (unsigned int)(~op);
        atomicMax(&g_best[c * NG + agi], key);
    }
    if (u1 && bg >= 0) {
        int bgi = si[bg];
        unsigned int op = (unsigned int)g_pidx[c * NP + j1];
        unsigned long long key =
            ((unsigned long long)g_sbits[c * NP + op] << 32) | (unsigned int)(~op);
        atomicMax(&g_best[c * NG + bgi], key);
    }
}

// ---------------- K6: per-class winner ranks + AP (fused) ----------------
__global__ void __launch_bounds__(1024) k_rankap() {
    __shared__ unsigned long long wkey[1024];
    __shared__ int    cnt[1026];
    __shared__ int    ssum[1024];
    __shared__ double red[1024];
    int c = blockIdx.x, t = threadIdx.x;

    unsigned long long k0 = (t < NG) ? g_best[c * NG + t] : 0ULL;
    wkey[t] = k0;
    ssum[t] = (k0 != 0ULL) ? 1 : 0;
    __syncthreads();
    // count winners
    for (int s = 512; s > 0; s >>= 1) {
        if (t < s) ssum[t] += ssum[t + s];
        __syncthreads();
    }
    int n_w = ssum[0];
    __syncthreads();

    // bitonic sort ascending: zeros (empties) land in front, winners in [off,1024)
    for (int k2 = 2; k2 <= 1024; k2 <<= 1) {
        for (int j = k2 >> 1; j > 0; j >>= 1) {
            int ixj = t ^ j;
            if (ixj > t) {
                bool up = ((t & k2) == 0);
                unsigned long long a = wkey[t], b = wkey[ixj];
                if ((a > b) == up) { wkey[t] = b; wkey[ixj] = a; }
            }
            __syncthreads();
        }
    }
    int off = 1024 - n_w;
    if (t <= n_w) cnt[t] = 0;
    __syncthreads();

    if (n_w > 0) {
        // every pred bins itself among the sorted winner keys
        for (int base = 0; base < NP; base += 1024) {
            int i = base + t;
            if (i < NP) {
                unsigned long long key =
                    ((unsigned long long)g_sbits[c * NP + i] << 32)
                    | (unsigned int)(~(unsigned int)i);
                int lo = off, n = n_w;
                while (n > 0) {
                    int half = n >> 1, mid = lo + half;
                    if (wkey[mid] < key) { lo = mid + 1; n -= half + 1; }
                    else n = half;
                }
                atomicAdd(&cnt[lo - off], 1);   // pos in [0, n_w]
            }
        }
    }
    __syncthreads();

    // inclusive suffix sum of cnt[0..n_w]
    ssum[t] = (t <= n_w) ? cnt[t] : 0;
    __syncthreads();
    for (int o2 = 1; o2 < 1024; o2 <<= 1) {
        int v = (t + o2 < 1024) ? ssum[t + o2] : 0;
        __syncthreads();
        ssum[t] += v;
        __syncthreads();
    }

    // winner j (ascending key) has rank r = ssum[j+1]; ctp at its rank = n_w - j
    double term = 0.0;
    if (t < n_w) {
        int r = ssum[t + 1];
        int ctp = n_w - t;
        if (r > 0) {
            float p1 = (float)ctp / (float)(r + 1);
            float p0 = (float)(ctp - 1) / (float)r;
            term = 0.5 * ((double)p1 + (double)p0);
        }
    }
    red[t] = term;
    __syncthreads();
    for (int s = 512; s > 0; s >>= 1) {
        if (t < s) red[t] += red[t + s];
        __syncthreads();
    }
    if (t == 0) g_ap[c] = (float)(red[0] / (double)NG);
}

// ---------------- K7: mean over classes ----------------
__global__ void k_mean(float* __restrict__ out) {
    __shared__ double red[128];
    int t = threadIdx.x;
    red[t] = (t < NC) ? (double)g_ap[t] : 0.0;
    __syncthreads();
    for (int s = 64; s > 0; s >>= 1) {
        if (t < s) red[t] += red[t + s];
        __syncthreads();
    }
    if (t == 0) out[0] = (float)(red[0] / (double)NC);
}

// ---------------- launcher ----------------
extern "C" void kernel_launch(void* const* d_in, const int* in_sizes, int n_in,
                              void* d_out, int out_size) {
    const float* pred;
    const float* gt;
    if (in_sizes[0] == NC * NP * 7) { pred = (const float*)d_in[0]; gt = (const float*)d_in[1]; }
    else                            { pred = (const float*)d_in[1]; gt = (const float*)d_in[0]; }

    const int NTOT = NC * NP;
    k_init<<<(NC * NG + 255) / 256, 256>>>();
    k_prep<<<(NTOT + 255) / 256, 256>>>(pred);
    k_xscan<<<NC, NPBIN>>>();
    k_fscatter<<<(NTOT + 255) / 256, 256>>>();
    k_gtsort<<<NC, 1024>>>(gt);
    dim3 mg((NP + PPB - 1) / PPB, NC);
    k_match<<<mg, MB>>>();
    k_rankap<<<NC, 1024>>>();
    k_mean<<<1, 128>>>((float*)d_out);
}